// round 9
// baseline (speedup 1.0000x reference)
#include <cuda_runtime.h>

#define BB 16
#define TT 4096
#define DD 512
#define GRID 148
#define NTHR 768
#define NWARP 24

// smem layout: [0, 150KB) tables; [150KB, +24*2KB) per-warp TMA staging
#define TBL_F4   (75 * 128)
#define BUF_OFF  (TBL_F4 * 16)

// PAD=10, BOS=11, EOS=12, ROW=13, SEP=14; digits 0..9

__device__ unsigned g_rc_t[TT * BB];        // [t][b] : r | c<<8 | tok<<16
__device__ float g_srow[30 * DD];
__device__ float g_scol[30 * DD];
__device__ unsigned g_scan_flag = 0;
__device__ unsigned g_pre_flag = 0;
__device__ unsigned g_done = 0;

// ---------------------------------------------------------------------------
// Packed transition-function monoid (2 words)
// ---------------------------------------------------------------------------
struct P { unsigned a, b; };

__device__ __forceinline__ P pidentity() { P p; p.a = 2u; p.b = 0u; return p; }

__device__ __forceinline__ P pcompose(P x, P y) {   // apply x, then y
    unsigned xg0 = x.a & 1u, xg1 = (x.a >> 1) & 1u;
    unsigned yg0 = y.a & 1u, yg1 = (y.a >> 1) & 1u;
    unsigned g0 = xg0 ? yg1 : yg0;
    unsigned g1 = xg1 ? yg1 : yg0;
    unsigned yrC = y.a & 4u;
    unsigned rV = yrC ? (y.a >> 8) : ((x.a >> 8) + (y.a >> 8));
    unsigned rC = (x.a & 4u) | yrC;
    unsigned xc0C = (x.a >> 3) & 1u, xc1C = (x.a >> 4) & 1u;
    unsigned yc0C = (y.a >> 3) & 1u, yc1C = (y.a >> 4) & 1u;
    unsigned xc0 = x.b & 0xffffu, xc1 = x.b >> 16;
    unsigned yc0 = y.b & 0xffffu, yc1 = y.b >> 16;
    unsigned bC0 = xg0 ? yc1C : yc0C;
    unsigned bV0 = xg0 ? yc1  : yc0;
    unsigned c0C = bC0 | xc0C;
    unsigned c0  = bC0 ? bV0 : xc0 + bV0;
    unsigned bC1 = xg1 ? yc1C : yc0C;
    unsigned bV1 = xg1 ? yc1  : yc0;
    unsigned c1C = bC1 | xc1C;
    unsigned c1  = bC1 ? bV1 : xc1 + bV1;
    P r;
    r.a = g0 | (g1 << 1) | rC | (c0C << 3) | (c1C << 4) | (rV << 8);
    r.b = c0 | (c1 << 16);
    return r;
}

__device__ __forceinline__ P pshfl_up(P p, int off) {
    P r;
    r.a = __shfl_up_sync(0xffffffffu, p.a, off);
    r.b = __shfl_up_sync(0xffffffffu, p.b, off);
    return r;
}

// ---------------------------------------------------------------------------
// Fused persistent kernel. grid=148 (all co-resident), 768 thr, ~199KB smem.
// Roles: blocks 0..15 scan; 16..79 precompute; ALL blocks then run main loop.
// Epilogue via STS + cp.async.bulk (TMA) instead of STG.128 (12cyc issue).
// ---------------------------------------------------------------------------
__global__ void __launch_bounds__(NTHR, 1) fused_kernel(
    const int* __restrict__ ids,
    const float* __restrict__ row_tab,   // (30, 256)
    const float* __restrict__ col_tab,   // (30, 256)
    const float* __restrict__ W,         // (512, 512) e-major
    const float* __restrict__ tok_tab,   // (15, 512)
    const float* __restrict__ pos_tab,   // (4096, 512)
    const float* __restrict__ gamma,
    const float* __restrict__ beta,
    float* __restrict__ out)
{
    extern __shared__ __align__(16) char s_raw[];
    const int tid = threadIdx.x;
    const int lane = tid & 31;
    const int warp = tid >> 5;

    // gamma/beta into registers early (independent of everything)
    float4 gm[4], bt[4];
    #pragma unroll
    for (int i = 0; i < 4; i++) {
        gm[i] = __ldg((const float4*)gamma + lane + i * 32);
        bt[i] = __ldg((const float4*)beta + lane + i * 32);
    }

    // ======================= ROLE PHASE =======================
    if (blockIdx.x < 16) {
        // ---------------- SCAN (512 active threads, 8 tok/thr) ----------------
        int* toks = (int*)s_raw;                   // [4096]
        P* warpTot = (P*)(s_raw + TT * 4);         // [16]
        P* warpPreInc = warpTot + 16;              // [16]

        const int b = blockIdx.x;
        const int* base = ids + b * TT;
        for (int i = tid; i < TT; i += NTHR) toks[i] = base[i];
        __syncthreads();

        P inc;
        if (tid < 512) {
            const int* my = toks + tid * 8;
            int fg0 = 0, fg1 = 1, frC = 0, frV = 0;
            int fc0C = 0, fc0 = 0, fc1C = 0, fc1 = 0;
            #pragma unroll
            for (int j = 0; j < 8; j++) {
                int tok = my[j];
                int bos = (tok == 11), sep = (tok == 14), rw = (tok == 13);
                int end = (tok == 12) | (tok == 10);
                int dig = (tok <= 9);
                if (bos | sep) { frC = 1; frV = 0; }
                else if (rw) frV++;
                {
                    int gc = fg0 & dig;
                    if (bos | sep | rw) { fc0C = 1; fc0 = 0; }
                    else if (gc) fc0++;
                    fg0 = bos ? 1 : (end ? 0 : fg0);
                }
                {
                    int gc = fg1 & dig;
                    if (bos | sep | rw) { fc1C = 1; fc1 = 0; }
                    else if (gc) fc1++;
                    fg1 = bos ? 1 : (end ? 0 : fg1);
                }
            }
            inc.a = (unsigned)fg0 | ((unsigned)fg1 << 1) | ((unsigned)frC << 2)
                  | ((unsigned)fc0C << 3) | ((unsigned)fc1C << 4) | ((unsigned)frV << 8);
            inc.b = (unsigned)fc0 | ((unsigned)fc1 << 16);

            #pragma unroll
            for (int off = 1; off < 32; off <<= 1) {
                P prev = pshfl_up(inc, off);
                if (lane >= off) inc = pcompose(prev, inc);
            }
            if (lane == 31) warpTot[warp] = inc;
        }
        __syncthreads();

        if (tid < 32) {
            P v = (tid < 16) ? warpTot[tid] : pidentity();
            #pragma unroll
            for (int off = 1; off < 16; off <<= 1) {
                P prev = pshfl_up(v, off);
                if (lane >= off) v = pcompose(prev, v);
            }
            if (tid < 16) warpPreInc[tid] = v;
        }
        __syncthreads();

        if (tid < 512) {
            P wex = pshfl_up(inc, 1);
            P base_p = (warp > 0) ? warpPreInc[warp - 1] : pidentity();
            P ex = (lane > 0) ? pcompose(base_p, wex) : base_p;
            int g = (int)(ex.a & 1u);
            int r = (int)(ex.a >> 8);
            int c = (int)(ex.b & 0xffffu);

            const int* my = toks + tid * 8;
            #pragma unroll
            for (int j = 0; j < 8; j++) {
                int tok = my[j];
                int bos = (tok == 11), sep = (tok == 14), rw = (tok == 13);
                int end = (tok == 12) | (tok == 10);
                int dig = (tok <= 9);
                int gc = g & dig;
                unsigned er = gc ? (unsigned)min(r, 29) : 0u;
                unsigned ec = gc ? (unsigned)min(c, 29) : 0u;
                g_rc_t[(tid * 8 + j) * BB + b] = er | (ec << 8) | ((unsigned)tok << 16);
                g = bos ? 1 : (end ? 0 : g);
                r = (bos | sep) ? 0 : (rw ? r + 1 : r);
                c = (bos | sep | rw) ? 0 : (gc ? c + 1 : c);
            }
        }
        __threadfence();
        __syncthreads();
        if (tid == 0) atomicAdd(&g_scan_flag, 1u);
    } else if (blockIdx.x < 80) {
        // ---------------- PRECOMPUTE (W read once total) ----------------
        float* tabs = (float*)s_raw;   // [60*256] : row_tab then col_tab
        {
            float4* t4 = (float4*)tabs;
            const float4* r4 = (const float4*)row_tab;
            const float4* c4 = (const float4*)col_tab;
            for (int i = tid; i < 30 * 64; i += NTHR) t4[i] = r4[i];
            for (int i = tid; i < 30 * 64; i += NTHR) t4[30 * 64 + i] = c4[i];
        }
        __syncthreads();

        const int task = (blockIdx.x - 16) * NWARP + warp;   // 64*24 = 1536 slots
        if (task < 1024) {
            const int e = task >> 1;
            const int half = task & 1;
            const float4* wp = (const float4*)(W + (size_t)e * DD + half * 256);
            const float4 w0 = __ldg(wp + lane * 2);
            const float4 w1 = __ldg(wp + lane * 2 + 1);
            float* dst = half ? g_scol : g_srow;
            const float* tb = tabs + half * 30 * 256;

            #pragma unroll 1
            for (int r = 0; r < 30; r += 2) {
                const float4* ta = (const float4*)(tb + r * 256);
                const float4* tc = (const float4*)(tb + (r + 1) * 256);
                float4 a0 = ta[lane * 2], a1 = ta[lane * 2 + 1];
                float4 b0 = tc[lane * 2], b1 = tc[lane * 2 + 1];
                float sA = a0.x * w0.x;
                sA = fmaf(a0.y, w0.y, sA); sA = fmaf(a0.z, w0.z, sA); sA = fmaf(a0.w, w0.w, sA);
                sA = fmaf(a1.x, w1.x, sA); sA = fmaf(a1.y, w1.y, sA);
                sA = fmaf(a1.z, w1.z, sA); sA = fmaf(a1.w, w1.w, sA);
                float sB = b0.x * w0.x;
                sB = fmaf(b0.y, w0.y, sB); sB = fmaf(b0.z, w0.z, sB); sB = fmaf(b0.w, w0.w, sB);
                sB = fmaf(b1.x, w1.x, sB); sB = fmaf(b1.y, w1.y, sB);
                sB = fmaf(b1.z, w1.z, sB); sB = fmaf(b1.w, w1.w, sB);
                #pragma unroll
                for (int o = 16; o > 0; o >>= 1) {
                    sA += __shfl_xor_sync(0xffffffffu, sA, o);
                    sB += __shfl_xor_sync(0xffffffffu, sB, o);
                }
                if (lane == 0) {
                    dst[r * DD + e] = sA;
                    dst[(r + 1) * DD + e] = sB;
                }
            }
        }
        __threadfence();
        __syncthreads();
        if (tid == 0) atomicAdd(&g_pre_flag, 1u);
    }

    // ======================= STAGE + SYNC =======================
    __syncthreads();   // role use of smem finished before overwrite
    float4* smv = (float4*)s_raw;   // tok[15*128] | srow[30*128] | scol[30*128]

    {
        const float4* t4 = (const float4*)tok_tab;
        for (int i = tid; i < 15 * 128; i += NTHR) smv[i] = t4[i];
    }
    if (tid == 0) {
        while (*(volatile unsigned*)&g_pre_flag < 64u) __nanosleep(64);
    }
    __syncthreads();
    {
        const float4* r4 = (const float4*)g_srow;
        for (int i = tid; i < 30 * 128; i += NTHR) smv[15 * 128 + i] = __ldcg(r4 + i);
        const float4* c4 = (const float4*)g_scol;
        for (int i = tid; i < 30 * 128; i += NTHR) smv[45 * 128 + i] = __ldcg(c4 + i);
    }
    if (tid == 0) {
        while (*(volatile unsigned*)&g_scan_flag < 16u) __nanosleep(64);
    }
    __syncthreads();

    // per-warp TMA staging buffer
    float4* wbuf = (float4*)(s_raw + BUF_OFF + warp * 2048);
    const unsigned wbuf_s = (unsigned)__cvta_generic_to_shared(wbuf);

    // ======================= MAIN LOOP =======================
    const int gw = warp * GRID + blockIdx.x;   // transposed striping
    const int NW = GRID * NWARP;               // 3552 warps

    for (int u = gw; u < TT * 4; u += NW) {
        const int t = u >> 2;
        const int q = u & 3;

        unsigned prl = 0;
        if (lane < 4) prl = __ldcg(g_rc_t + t * BB + q * 4 + lane);
        const float4* pp = (const float4*)(pos_tab + (size_t)t * DD);
        float4 pos0 = __ldg(pp + lane);
        float4 pos1 = __ldg(pp + lane + 32);
        float4 pos2 = __ldg(pp + lane + 64);
        float4 pos3 = __ldg(pp + lane + 96);
        const float4 pos[4] = { pos0, pos1, pos2, pos3 };

        #pragma unroll 1
        for (int j = 0; j < 4; j++) {
            const unsigned w = __shfl_sync(0xffffffffu, prl, j);
            const int r = w & 0xff;
            const int c = (w >> 8) & 0xff;
            const int tok = w >> 16;

            const float4* tp = smv + tok * 128;
            float4 x[4];

            if (tok <= 9) {   // warp-uniform
                const float4* rp = smv + 15 * 128 + r * 128;
                const float4* cp = smv + 45 * 128 + c * 128;
                #pragma unroll
                for (int i = 0; i < 4; i++) {
                    const int idx = lane + i * 32;
                    float4 a = tp[idx];
                    float4 rr = rp[idx];
                    float4 cc = cp[idx];
                    float4 v;
                    v.x = (a.x + pos[i].x) + (rr.x + cc.x);
                    v.y = (a.y + pos[i].y) + (rr.y + cc.y);
                    v.z = (a.z + pos[i].z) + (rr.z + cc.z);
                    v.w = (a.w + pos[i].w) + (rr.w + cc.w);
                    x[i] = v;
                }
            } else {
                #pragma unroll
                for (int i = 0; i < 4; i++) {
                    const int idx = lane + i * 32;
                    float4 a = tp[idx];
                    float4 v;
                    v.x = a.x + pos[i].x;
                    v.y = a.y + pos[i].y;
                    v.z = a.z + pos[i].z;
                    v.w = a.w + pos[i].w;
                    x[i] = v;
                }
            }

            float sum = 0.f, sq = 0.f;
            #pragma unroll
            for (int i = 0; i < 4; i++) {
                sum += (x[i].x + x[i].y) + (x[i].z + x[i].w);
                sq = fmaf(x[i].x, x[i].x, sq);
                sq = fmaf(x[i].y, x[i].y, sq);
                sq = fmaf(x[i].z, x[i].z, sq);
                sq = fmaf(x[i].w, x[i].w, sq);
            }

            #pragma unroll
            for (int o = 16; o > 0; o >>= 1) {
                sum += __shfl_xor_sync(0xffffffffu, sum, o);
                sq  += __shfl_xor_sync(0xffffffffu, sq,  o);
            }

            const float mu = sum * (1.f / (float)DD);
            const float var = sq * (1.f / (float)DD) - mu * mu;
            const float inv = rsqrtf(var + 1e-5f);

            // ---- epilogue: STS into staging buffer, then 1D TMA bulk store ----
            // ensure previous bulk copy has finished READING this buffer
            if (lane == 0)
                asm volatile("cp.async.bulk.wait_group.read 0;" ::: "memory");
            __syncwarp();

            #pragma unroll
            for (int i = 0; i < 4; i++) {
                float4 v = x[i];
                v.x = fmaf((v.x - mu) * inv, gm[i].x, bt[i].x);
                v.y = fmaf((v.y - mu) * inv, gm[i].y, bt[i].y);
                v.z = fmaf((v.z - mu) * inv, gm[i].z, bt[i].z);
                v.w = fmaf((v.w - mu) * inv, gm[i].w, bt[i].w);
                wbuf[lane + i * 32] = v;
            }
            asm volatile("fence.proxy.async.shared::cta;" ::: "memory");
            __syncwarp();
            if (lane == 0) {
                float* gdst = out + (size_t)((q * 4 + j) * TT + t) * DD;
                asm volatile(
                    "cp.async.bulk.global.shared::cta.bulk_group [%0], [%1], %2;"
                    :: "l"(gdst), "r"(wbuf_s), "r"(2048) : "memory");
                asm volatile("cp.async.bulk.commit_group;" ::: "memory");
            }
        }
    }

    // drain all outstanding TMA stores before exit
    if (lane == 0)
        asm volatile("cp.async.bulk.wait_group 0;" ::: "memory");
    __syncwarp();

    // ======================= FLAG RESET (replay-safe) =======================
    __syncthreads();
    if (tid == 0) {
        __threadfence();
        if (atomicAdd(&g_done, 1u) == GRID - 1) {
            g_scan_flag = 0;
            g_pre_flag = 0;
            __threadfence();
            g_done = 0;
        }
    }
}

// ---------------------------------------------------------------------------
extern "C" void kernel_launch(void* const* d_in, const int* in_sizes, int n_in,
                              void* d_out, int out_size) {
    const int*   ids   = (const int*)  d_in[0];
    const float* tokt  = (const float*)d_in[1];
    const float* post  = (const float*)d_in[2];
    const float* rowt  = (const float*)d_in[3];
    const float* colt  = (const float*)d_in[4];
    const float* W     = (const float*)d_in[5];
    const float* gamma = (const float*)d_in[6];
    const float* beta  = (const float*)d_in[7];
    float* out = (float*)d_out;
    (void)in_sizes; (void)n_in; (void)out_size;

    const int smem_bytes = BUF_OFF + NWARP * 2048;   // 153600 + 49152 = 202752 B
    cudaFuncSetAttribute(fused_kernel,
                         cudaFuncAttributeMaxDynamicSharedMemorySize, smem_bytes);

    fused_kernel<<<GRID, NTHR, smem_bytes>>>(ids, rowt, colt, W,
                                             tokt, post, gamma, beta, out);
}

// round 11
// speedup vs baseline: 1.1791x; 1.1791x over previous
#include <cuda_runtime.h>

#define BB 16
#define TT 4096
#define DD 512
#define GRID 148
#define NTHR 1024
#define NWARP 32

// PAD=10, BOS=11, EOS=12, ROW=13, SEP=14; digits 0..9

__device__ unsigned g_rc_t[TT * BB];        // [t][b] : r | c<<8 | tok<<16
__device__ float g_srow[30 * DD];
__device__ float g_scol[30 * DD];
__device__ unsigned g_scan_flag = 0;
__device__ unsigned g_pre_flag = 0;
__device__ unsigned g_done = 0;

// ---------------------------------------------------------------------------
// Packed transition-function monoid (2 words)
// ---------------------------------------------------------------------------
struct P { unsigned a, b; };

__device__ __forceinline__ P pidentity() { P p; p.a = 2u; p.b = 0u; return p; }

__device__ __forceinline__ P pcompose(P x, P y) {   // apply x, then y
    unsigned xg0 = x.a & 1u, xg1 = (x.a >> 1) & 1u;
    unsigned yg0 = y.a & 1u, yg1 = (y.a >> 1) & 1u;
    unsigned g0 = xg0 ? yg1 : yg0;
    unsigned g1 = xg1 ? yg1 : yg0;
    unsigned yrC = y.a & 4u;
    unsigned rV = yrC ? (y.a >> 8) : ((x.a >> 8) + (y.a >> 8));
    unsigned rC = (x.a & 4u) | yrC;
    unsigned xc0C = (x.a >> 3) & 1u, xc1C = (x.a >> 4) & 1u;
    unsigned yc0C = (y.a >> 3) & 1u, yc1C = (y.a >> 4) & 1u;
    unsigned xc0 = x.b & 0xffffu, xc1 = x.b >> 16;
    unsigned yc0 = y.b & 0xffffu, yc1 = y.b >> 16;
    unsigned bC0 = xg0 ? yc1C : yc0C;
    unsigned bV0 = xg0 ? yc1  : yc0;
    unsigned c0C = bC0 | xc0C;
    unsigned c0  = bC0 ? bV0 : xc0 + bV0;
    unsigned bC1 = xg1 ? yc1C : yc0C;
    unsigned bV1 = xg1 ? yc1  : yc0;
    unsigned c1C = bC1 | xc1C;
    unsigned c1  = bC1 ? bV1 : xc1 + bV1;
    P r;
    r.a = g0 | (g1 << 1) | rC | (c0C << 3) | (c1C << 4) | (rV << 8);
    r.b = c0 | (c1 << 16);
    return r;
}

__device__ __forceinline__ P pshfl_up(P p, int off) {
    P r;
    r.a = __shfl_up_sync(0xffffffffu, p.a, off);
    r.b = __shfl_up_sync(0xffffffffu, p.b, off);
    return r;
}

// ---------------------------------------------------------------------------
// Fused persistent kernel. grid=148, 1024 thr (32 warps), ~158KB smem.
// Roles: blocks 0..15 scan; 16..79 precompute; ALL blocks then run main loop.
// ---------------------------------------------------------------------------
__global__ void __launch_bounds__(NTHR, 1) fused_kernel(
    const int* __restrict__ ids,
    const float* __restrict__ row_tab,   // (30, 256)
    const float* __restrict__ col_tab,   // (30, 256)
    const float* __restrict__ W,         // (512, 512) e-major
    const float* __restrict__ tok_tab,   // (15, 512)
    const float* __restrict__ pos_tab,   // (4096, 512)
    const float* __restrict__ gamma,
    const float* __restrict__ beta,
    float* __restrict__ out)
{
    extern __shared__ __align__(16) char s_raw[];
    const int tid = threadIdx.x;
    const int lane = tid & 31;
    const int warp = tid >> 5;

    // ======================= ROLE PHASE =======================
    if (blockIdx.x < 16) {
        // ---------------- SCAN (512 active threads, 8 tok/thr) ----------------
        int* toks = (int*)s_raw;                   // [4096]
        P* warpTot = (P*)(s_raw + TT * 4);         // [16]
        P* warpPreInc = warpTot + 16;              // [16]

        const int b = blockIdx.x;
        const int* base = ids + b * TT;
        for (int i = tid; i < TT; i += NTHR) toks[i] = base[i];
        __syncthreads();

        P inc;
        if (tid < 512) {
            const int* my = toks + tid * 8;
            int fg0 = 0, fg1 = 1, frC = 0, frV = 0;
            int fc0C = 0, fc0 = 0, fc1C = 0, fc1 = 0;
            #pragma unroll
            for (int j = 0; j < 8; j++) {
                int tok = my[j];
                int bos = (tok == 11), sep = (tok == 14), rw = (tok == 13);
                int end = (tok == 12) | (tok == 10);
                int dig = (tok <= 9);
                if (bos | sep) { frC = 1; frV = 0; }
                else if (rw) frV++;
                {
                    int gc = fg0 & dig;
                    if (bos | sep | rw) { fc0C = 1; fc0 = 0; }
                    else if (gc) fc0++;
                    fg0 = bos ? 1 : (end ? 0 : fg0);
                }
                {
                    int gc = fg1 & dig;
                    if (bos | sep | rw) { fc1C = 1; fc1 = 0; }
                    else if (gc) fc1++;
                    fg1 = bos ? 1 : (end ? 0 : fg1);
                }
            }
            inc.a = (unsigned)fg0 | ((unsigned)fg1 << 1) | ((unsigned)frC << 2)
                  | ((unsigned)fc0C << 3) | ((unsigned)fc1C << 4) | ((unsigned)frV << 8);
            inc.b = (unsigned)fc0 | ((unsigned)fc1 << 16);

            #pragma unroll
            for (int off = 1; off < 32; off <<= 1) {
                P prev = pshfl_up(inc, off);
                if (lane >= off) inc = pcompose(prev, inc);
            }
            if (lane == 31) warpTot[warp] = inc;
        }
        __syncthreads();

        if (tid < 32) {
            P v = (tid < 16) ? warpTot[tid] : pidentity();
            #pragma unroll
            for (int off = 1; off < 16; off <<= 1) {
                P prev = pshfl_up(v, off);
                if (lane >= off) v = pcompose(prev, v);
            }
            if (tid < 16) warpPreInc[tid] = v;
        }
        __syncthreads();

        if (tid < 512) {
            P wex = pshfl_up(inc, 1);
            P base_p = (warp > 0) ? warpPreInc[warp - 1] : pidentity();
            P ex = (lane > 0) ? pcompose(base_p, wex) : base_p;
            int g = (int)(ex.a & 1u);
            int r = (int)(ex.a >> 8);
            int c = (int)(ex.b & 0xffffu);

            const int* my = toks + tid * 8;
            #pragma unroll
            for (int j = 0; j < 8; j++) {
                int tok = my[j];
                int bos = (tok == 11), sep = (tok == 14), rw = (tok == 13);
                int end = (tok == 12) | (tok == 10);
                int dig = (tok <= 9);
                int gc = g & dig;
                unsigned er = gc ? (unsigned)min(r, 29) : 0u;
                unsigned ec = gc ? (unsigned)min(c, 29) : 0u;
                g_rc_t[(tid * 8 + j) * BB + b] = er | (ec << 8) | ((unsigned)tok << 16);
                g = bos ? 1 : (end ? 0 : g);
                r = (bos | sep) ? 0 : (rw ? r + 1 : r);
                c = (bos | sep | rw) ? 0 : (gc ? c + 1 : c);
            }
        }
        __threadfence();
        __syncthreads();
        if (tid == 0) atomicAdd(&g_scan_flag, 1u);
    } else if (blockIdx.x < 80) {
        // ---------------- PRECOMPUTE (W read once total) ----------------
        float* tabs = (float*)s_raw;   // [60*256] : row_tab then col_tab
        {
            float4* t4 = (float4*)tabs;
            const float4* r4 = (const float4*)row_tab;
            const float4* c4 = (const float4*)col_tab;
            for (int i = tid; i < 30 * 64; i += NTHR) t4[i] = r4[i];
            for (int i = tid; i < 30 * 64; i += NTHR) t4[30 * 64 + i] = c4[i];
        }
        __syncthreads();

        const int task = (blockIdx.x - 16) * 16 + warp;   // 64 blocks x first 16 warps
        if (warp < 16 && task < 1024) {
            const int e = task >> 1;
            const int half = task & 1;
            const float4* wp = (const float4*)(W + (size_t)e * DD + half * 256);
            const float4 w0 = __ldg(wp + lane * 2);
            const float4 w1 = __ldg(wp + lane * 2 + 1);
            float* dst = half ? g_scol : g_srow;
            const float* tb = tabs + half * 30 * 256;

            #pragma unroll 1
            for (int r = 0; r < 30; r += 2) {
                const float4* ta = (const float4*)(tb + r * 256);
                const float4* tc = (const float4*)(tb + (r + 1) * 256);
                float4 a0 = ta[lane * 2], a1 = ta[lane * 2 + 1];
                float4 b0 = tc[lane * 2], b1 = tc[lane * 2 + 1];
                float sA = a0.x * w0.x;
                sA = fmaf(a0.y, w0.y, sA); sA = fmaf(a0.z, w0.z, sA); sA = fmaf(a0.w, w0.w, sA);
                sA = fmaf(a1.x, w1.x, sA); sA = fmaf(a1.y, w1.y, sA);
                sA = fmaf(a1.z, w1.z, sA); sA = fmaf(a1.w, w1.w, sA);
                float sB = b0.x * w0.x;
                sB = fmaf(b0.y, w0.y, sB); sB = fmaf(b0.z, w0.z, sB); sB = fmaf(b0.w, w0.w, sB);
                sB = fmaf(b1.x, w1.x, sB); sB = fmaf(b1.y, w1.y, sB);
                sB = fmaf(b1.z, w1.z, sB); sB = fmaf(b1.w, w1.w, sB);
                #pragma unroll
                for (int o = 16; o > 0; o >>= 1) {
                    sA += __shfl_xor_sync(0xffffffffu, sA, o);
                    sB += __shfl_xor_sync(0xffffffffu, sB, o);
                }
                if (lane == 0) {
                    dst[r * DD + e] = sA;
                    dst[(r + 1) * DD + e] = sB;
                }
            }
        }
        __threadfence();
        __syncthreads();
        if (tid == 0) atomicAdd(&g_pre_flag, 1u);
    }

    // ======================= STAGE + SYNC =======================
    __syncthreads();   // role use of smem finished before overwrite
    float4* smv = (float4*)s_raw;   // tok[15*128]|srow[30*128]|scol[30*128]|g[128]|b[128]

    {
        const float4* t4 = (const float4*)tok_tab;
        for (int i = tid; i < 15 * 128; i += NTHR) smv[i] = t4[i];
        if (tid < 128) smv[75 * 128 + tid] = ((const float4*)gamma)[tid];
        else if (tid < 256) smv[76 * 128 + (tid - 128)] = ((const float4*)beta)[tid - 128];
    }
    if (tid == 0) {
        while (*(volatile unsigned*)&g_pre_flag < 64u) __nanosleep(64);
    }
    __syncthreads();
    {
        const float4* r4 = (const float4*)g_srow;
        for (int i = tid; i < 30 * 128; i += NTHR) smv[15 * 128 + i] = __ldcg(r4 + i);
        const float4* c4 = (const float4*)g_scol;
        for (int i = tid; i < 30 * 128; i += NTHR) smv[45 * 128 + i] = __ldcg(c4 + i);
    }
    if (tid == 0) {
        while (*(volatile unsigned*)&g_scan_flag < 16u) __nanosleep(64);
    }
    __syncthreads();

    // ======================= MAIN LOOP =======================
    const float4* gam_s = smv + 75 * 128;
    const float4* bet_s = smv + 76 * 128;
    const int gw = warp * GRID + blockIdx.x;   // transposed striping
    const int NW = GRID * NWARP;               // 4736 warps

    for (int u = gw; u < TT * 4; u += NW) {
        const int t = u >> 2;
        const int q = u & 3;

        unsigned prl = 0;
        if (lane < 4) prl = __ldcg(g_rc_t + t * BB + q * 4 + lane);
        const float4* pp = (const float4*)(pos_tab + (size_t)t * DD);
        float4 pos0 = __ldg(pp + lane);
        float4 pos1 = __ldg(pp + lane + 32);
        float4 pos2 = __ldg(pp + lane + 64);
        float4 pos3 = __ldg(pp + lane + 96);
        const float4 pos[4] = { pos0, pos1, pos2, pos3 };

        #pragma unroll 1
        for (int j = 0; j < 4; j++) {
            const unsigned w = __shfl_sync(0xffffffffu, prl, j);
            const int r = w & 0xff;
            const int c = (w >> 8) & 0xff;
            const int tok = w >> 16;

            const float4* tp = smv + tok * 128;
            float4 x[4];

            if (tok <= 9) {   // warp-uniform
                const float4* rp = smv + 15 * 128 + r * 128;
                const float4* cp = smv + 45 * 128 + c * 128;
                #pragma unroll
                for (int i = 0; i < 4; i++) {
                    const int idx = lane + i * 32;
                    float4 a = tp[idx];
                    float4 rr = rp[idx];
                    float4 cc = cp[idx];
                    float4 v;
                    v.x = (a.x + pos[i].x) + (rr.x + cc.x);
                    v.y = (a.y + pos[i].y) + (rr.y + cc.y);
                    v.z = (a.z + pos[i].z) + (rr.z + cc.z);
                    v.w = (a.w + pos[i].w) + (rr.w + cc.w);
                    x[i] = v;
                }
            } else {
                #pragma unroll
                for (int i = 0; i < 4; i++) {
                    const int idx = lane + i * 32;
                    float4 a = tp[idx];
                    float4 v;
                    v.x = a.x + pos[i].x;
                    v.y = a.y + pos[i].y;
                    v.z = a.z + pos[i].z;
                    v.w = a.w + pos[i].w;
                    x[i] = v;
                }
            }

            float sum = 0.f, sq = 0.f;
            #pragma unroll
            for (int i = 0; i < 4; i++) {
                sum += (x[i].x + x[i].y) + (x[i].z + x[i].w);
                sq = fmaf(x[i].x, x[i].x, sq);
                sq = fmaf(x[i].y, x[i].y, sq);
                sq = fmaf(x[i].z, x[i].z, sq);
                sq = fmaf(x[i].w, x[i].w, sq);
            }

            #pragma unroll
            for (int o = 16; o > 0; o >>= 1) {
                sum += __shfl_xor_sync(0xffffffffu, sum, o);
                sq  += __shfl_xor_sync(0xffffffffu, sq,  o);
            }

            const float mu = sum * (1.f / (float)DD);
            const float var = sq * (1.f / (float)DD) - mu * mu;
            const float inv = rsqrtf(var + 1e-5f);

            float4* op = (float4*)(out + (size_t)((q * 4 + j) * TT + t) * DD);
            #pragma unroll
            for (int i = 0; i < 4; i++) {
                const int idx = lane + i * 32;
                float4 gmv = gam_s[idx];
                float4 btv = bet_s[idx];
                float4 v = x[i];
                v.x = fmaf((v.x - mu) * inv, gmv.x, btv.x);
                v.y = fmaf((v.y - mu) * inv, gmv.y, btv.y);
                v.z = fmaf((v.z - mu) * inv, gmv.z, btv.z);
                v.w = fmaf((v.w - mu) * inv, gmv.w, btv.w);
                __stcs(op + idx, v);
            }
        }
    }

    // ======================= FLAG RESET (replay-safe) =======================
    __syncthreads();
    if (tid == 0) {
        __threadfence();
        if (atomicAdd(&g_done, 1u) == GRID - 1) {
            g_scan_flag = 0;
            g_pre_flag = 0;
            __threadfence();
            g_done = 0;
        }
    }
}

// ---------------------------------------------------------------------------
extern "C" void kernel_launch(void* const* d_in, const int* in_sizes, int n_in,
                              void* d_out, int out_size) {
    const int*   ids   = (const int*)  d_in[0];
    const float* tokt  = (const float*)d_in[1];
    const float* post  = (const float*)d_in[2];
    const float* rowt  = (const float*)d_in[3];
    const float* colt  = (const float*)d_in[4];
    const float* W     = (const float*)d_in[5];
    const float* gamma = (const float*)d_in[6];
    const float* beta  = (const float*)d_in[7];
    float* out = (float*)d_out;
    (void)in_sizes; (void)n_in; (void)out_size;

    const int smem_bytes = 77 * 128 * 16;   // 157,696 B
    cudaFuncSetAttribute(fused_kernel,
                         cudaFuncAttributeMaxDynamicSharedMemorySize, smem_bytes);

    fused_kernel<<<GRID, NTHR, smem_bytes>>>(ids, rowt, colt, W,
                                             tokt, post, gamma, beta, out);
}

// round 12
// speedup vs baseline: 1.1993x; 1.0171x over previous
#include <cuda_runtime.h>

#define BB 16
#define TT 4096
#define DD 512
#define GRID 148
#define NTHR 768
#define NWARP 24
#define NCOMB 9005   // 10*30*30 digit combos + 5 non-digit tokens

// PAD=10, BOS=11, EOS=12, ROW=13, SEP=14; digits 0..9

__device__ unsigned g_rc_t[TT * BB];        // [t][b] : r | c<<8 | tok<<16
__device__ float g_srow[30 * DD];
__device__ float g_scol[30 * DD];
__device__ float g_comb[(size_t)NCOMB * DD];   // 18.44 MB, L2-resident
__device__ unsigned g_scan_flag = 0;
__device__ unsigned g_pre_flag = 0;
__device__ unsigned g_comb_flag = 0;
__device__ unsigned g_done = 0;

// ---------------------------------------------------------------------------
// Packed transition-function monoid (2 words)
// ---------------------------------------------------------------------------
struct P { unsigned a, b; };

__device__ __forceinline__ P pidentity() { P p; p.a = 2u; p.b = 0u; return p; }

__device__ __forceinline__ P pcompose(P x, P y) {   // apply x, then y
    unsigned xg0 = x.a & 1u, xg1 = (x.a >> 1) & 1u;
    unsigned yg0 = y.a & 1u, yg1 = (y.a >> 1) & 1u;
    unsigned g0 = xg0 ? yg1 : yg0;
    unsigned g1 = xg1 ? yg1 : yg0;
    unsigned yrC = y.a & 4u;
    unsigned rV = yrC ? (y.a >> 8) : ((x.a >> 8) + (y.a >> 8));
    unsigned rC = (x.a & 4u) | yrC;
    unsigned xc0C = (x.a >> 3) & 1u, xc1C = (x.a >> 4) & 1u;
    unsigned yc0C = (y.a >> 3) & 1u, yc1C = (y.a >> 4) & 1u;
    unsigned xc0 = x.b & 0xffffu, xc1 = x.b >> 16;
    unsigned yc0 = y.b & 0xffffu, yc1 = y.b >> 16;
    unsigned bC0 = xg0 ? yc1C : yc0C;
    unsigned bV0 = xg0 ? yc1  : yc0;
    unsigned c0C = bC0 | xc0C;
    unsigned c0  = bC0 ? bV0 : xc0 + bV0;
    unsigned bC1 = xg1 ? yc1C : yc0C;
    unsigned bV1 = xg1 ? yc1  : yc0;
    unsigned c1C = bC1 | xc1C;
    unsigned c1  = bC1 ? bV1 : xc1 + bV1;
    P r;
    r.a = g0 | (g1 << 1) | rC | (c0C << 3) | (c1C << 4) | (rV << 8);
    r.b = c0 | (c1 << 16);
    return r;
}

__device__ __forceinline__ P pshfl_up(P p, int off) {
    P r;
    r.a = __shfl_up_sync(0xffffffffu, p.a, off);
    r.b = __shfl_up_sync(0xffffffffu, p.b, off);
    return r;
}

// ---------------------------------------------------------------------------
// Fused persistent kernel. grid=148, 768 thr, 61KB smem (prep phases only).
// Phases: [role: scan | srow/scol] -> [all: build g_comb] -> [all: main].
// ---------------------------------------------------------------------------
__global__ void __launch_bounds__(NTHR, 1) fused_kernel(
    const int* __restrict__ ids,
    const float* __restrict__ row_tab,   // (30, 256)
    const float* __restrict__ col_tab,   // (30, 256)
    const float* __restrict__ W,         // (512, 512) e-major
    const float* __restrict__ tok_tab,   // (15, 512)
    const float* __restrict__ pos_tab,   // (4096, 512)
    const float* __restrict__ gamma,
    const float* __restrict__ beta,
    float* __restrict__ out)
{
    extern __shared__ __align__(16) char s_raw[];
    const int tid = threadIdx.x;
    const int lane = tid & 31;
    const int warp = tid >> 5;

    // gamma/beta into registers (loop-invariant, no smem => no per-row LDS)
    float4 gm[4], bt[4];
    #pragma unroll
    for (int i = 0; i < 4; i++) {
        gm[i] = __ldg((const float4*)gamma + lane + i * 32);
        bt[i] = __ldg((const float4*)beta + lane + i * 32);
    }

    // ======================= ROLE PHASE =======================
    if (blockIdx.x < 16) {
        // ---------------- SCAN (512 active threads, 8 tok/thr) ----------------
        int* toks = (int*)s_raw;                   // [4096]
        P* warpTot = (P*)(s_raw + TT * 4);         // [16]
        P* warpPreInc = warpTot + 16;              // [16]

        const int b = blockIdx.x;
        const int* base = ids + b * TT;
        for (int i = tid; i < TT; i += NTHR) toks[i] = base[i];
        __syncthreads();

        P inc;
        if (tid < 512) {
            const int* my = toks + tid * 8;
            int fg0 = 0, fg1 = 1, frC = 0, frV = 0;
            int fc0C = 0, fc0 = 0, fc1C = 0, fc1 = 0;
            #pragma unroll
            for (int j = 0; j < 8; j++) {
                int tok = my[j];
                int bos = (tok == 11), sep = (tok == 14), rw = (tok == 13);
                int end = (tok == 12) | (tok == 10);
                int dig = (tok <= 9);
                if (bos | sep) { frC = 1; frV = 0; }
                else if (rw) frV++;
                {
                    int gc = fg0 & dig;
                    if (bos | sep | rw) { fc0C = 1; fc0 = 0; }
                    else if (gc) fc0++;
                    fg0 = bos ? 1 : (end ? 0 : fg0);
                }
                {
                    int gc = fg1 & dig;
                    if (bos | sep | rw) { fc1C = 1; fc1 = 0; }
                    else if (gc) fc1++;
                    fg1 = bos ? 1 : (end ? 0 : fg1);
                }
            }
            inc.a = (unsigned)fg0 | ((unsigned)fg1 << 1) | ((unsigned)frC << 2)
                  | ((unsigned)fc0C << 3) | ((unsigned)fc1C << 4) | ((unsigned)frV << 8);
            inc.b = (unsigned)fc0 | ((unsigned)fc1 << 16);

            #pragma unroll
            for (int off = 1; off < 32; off <<= 1) {
                P prev = pshfl_up(inc, off);
                if (lane >= off) inc = pcompose(prev, inc);
            }
            if (lane == 31) warpTot[warp] = inc;
        }
        __syncthreads();

        if (tid < 32) {
            P v = (tid < 16) ? warpTot[tid] : pidentity();
            #pragma unroll
            for (int off = 1; off < 16; off <<= 1) {
                P prev = pshfl_up(v, off);
                if (lane >= off) v = pcompose(prev, v);
            }
            if (tid < 16) warpPreInc[tid] = v;
        }
        __syncthreads();

        if (tid < 512) {
            P wex = pshfl_up(inc, 1);
            P base_p = (warp > 0) ? warpPreInc[warp - 1] : pidentity();
            P ex = (lane > 0) ? pcompose(base_p, wex) : base_p;
            int g = (int)(ex.a & 1u);
            int r = (int)(ex.a >> 8);
            int c = (int)(ex.b & 0xffffu);

            const int* my = toks + tid * 8;
            #pragma unroll
            for (int j = 0; j < 8; j++) {
                int tok = my[j];
                int bos = (tok == 11), sep = (tok == 14), rw = (tok == 13);
                int end = (tok == 12) | (tok == 10);
                int dig = (tok <= 9);
                int gc = g & dig;
                unsigned er = gc ? (unsigned)min(r, 29) : 0u;
                unsigned ec = gc ? (unsigned)min(c, 29) : 0u;
                g_rc_t[(tid * 8 + j) * BB + b] = er | (ec << 8) | ((unsigned)tok << 16);
                g = bos ? 1 : (end ? 0 : g);
                r = (bos | sep) ? 0 : (rw ? r + 1 : r);
                c = (bos | sep | rw) ? 0 : (gc ? c + 1 : c);
            }
        }
        __threadfence();
        __syncthreads();
        if (tid == 0) atomicAdd(&g_scan_flag, 1u);
    } else if (blockIdx.x < 80) {
        // ---------------- srow/scol PRECOMPUTE (W read once total) ----------------
        float* tabs = (float*)s_raw;   // [60*256] : row_tab then col_tab
        {
            float4* t4 = (float4*)tabs;
            const float4* r4 = (const float4*)row_tab;
            const float4* c4 = (const float4*)col_tab;
            for (int i = tid; i < 30 * 64; i += NTHR) t4[i] = r4[i];
            for (int i = tid; i < 30 * 64; i += NTHR) t4[30 * 64 + i] = c4[i];
        }
        __syncthreads();

        const int task = (blockIdx.x - 16) * 16 + warp;   // 64 blocks x 16 warps
        if (warp < 16 && task < 1024) {
            const int e = task >> 1;
            const int half = task & 1;
            const float4* wp = (const float4*)(W + (size_t)e * DD + half * 256);
            const float4 w0 = __ldg(wp + lane * 2);
            const float4 w1 = __ldg(wp + lane * 2 + 1);
            float* dst = half ? g_scol : g_srow;
            const float* tb = tabs + half * 30 * 256;

            #pragma unroll 1
            for (int r = 0; r < 30; r += 2) {
                const float4* ta = (const float4*)(tb + r * 256);
                const float4* tc = (const float4*)(tb + (r + 1) * 256);
                float4 a0 = ta[lane * 2], a1 = ta[lane * 2 + 1];
                float4 b0 = tc[lane * 2], b1 = tc[lane * 2 + 1];
                float sA = a0.x * w0.x;
                sA = fmaf(a0.y, w0.y, sA); sA = fmaf(a0.z, w0.z, sA); sA = fmaf(a0.w, w0.w, sA);
                sA = fmaf(a1.x, w1.x, sA); sA = fmaf(a1.y, w1.y, sA);
                sA = fmaf(a1.z, w1.z, sA); sA = fmaf(a1.w, w1.w, sA);
                float sB = b0.x * w0.x;
                sB = fmaf(b0.y, w0.y, sB); sB = fmaf(b0.z, w0.z, sB); sB = fmaf(b0.w, w0.w, sB);
                sB = fmaf(b1.x, w1.x, sB); sB = fmaf(b1.y, w1.y, sB);
                sB = fmaf(b1.z, w1.z, sB); sB = fmaf(b1.w, w1.w, sB);
                #pragma unroll
                for (int o = 16; o > 0; o >>= 1) {
                    sA += __shfl_xor_sync(0xffffffffu, sA, o);
                    sB += __shfl_xor_sync(0xffffffffu, sB, o);
                }
                if (lane == 0) {
                    dst[r * DD + e] = sA;
                    dst[(r + 1) * DD + e] = sB;
                }
            }
        }
        __threadfence();
        __syncthreads();
        if (tid == 0) atomicAdd(&g_pre_flag, 1u);
    }

    // ======================= BUILD COMBINED TABLE =======================
    // comb[tok*900 + r*30 + c] = tok_tab[tok] + srow[r] + scol[c]  (digits)
    // comb[9000 + tok-10]      = tok_tab[tok]                      (non-digit)
    if (tid == 0) {
        while (*(volatile unsigned*)&g_pre_flag < 64u) __nanosleep(64);
    }
    __syncthreads();
    {
        const int grp = tid >> 7;        // 6 groups of 128 threads
        const int gt = tid & 127;        // float4 index within row
        for (int combo = blockIdx.x * 6 + grp; combo < NCOMB; combo += GRID * 6) {
            float4* dst = (float4*)(g_comb + (size_t)combo * DD);
            if (combo < 9000) {
                const int tok = combo / 900;
                const int rem = combo - tok * 900;
                const int r = rem / 30;
                const int c = rem - r * 30;
                float4 t = __ldg((const float4*)(tok_tab + tok * DD) + gt);
                float4 rr = __ldcg((const float4*)(g_srow + r * DD) + gt);
                float4 cc = __ldcg((const float4*)(g_scol + c * DD) + gt);
                float4 v;
                v.x = t.x + rr.x + cc.x;
                v.y = t.y + rr.y + cc.y;
                v.z = t.z + rr.z + cc.z;
                v.w = t.w + rr.w + cc.w;
                dst[gt] = v;
            } else {
                const int tok = combo - 9000 + 10;
                dst[gt] = __ldg((const float4*)(tok_tab + tok * DD) + gt);
            }
        }
    }
    __threadfence();
    __syncthreads();
    if (tid == 0) {
        atomicAdd(&g_comb_flag, 1u);
        while (*(volatile unsigned*)&g_comb_flag < (unsigned)GRID) __nanosleep(64);
        while (*(volatile unsigned*)&g_scan_flag < 16u) __nanosleep(64);
    }
    __syncthreads();

    // ======================= MAIN LOOP =======================
    const int gw = warp * GRID + blockIdx.x;   // transposed striping
    const int NW = GRID * NWARP;               // 3552 warps

    for (int u = gw; u < TT * 4; u += NW) {
        const int t = u >> 2;
        const int q = u & 3;

        unsigned prl = 0;
        if (lane < 4) prl = __ldcg(g_rc_t + t * BB + q * 4 + lane);
        const float4* pp = (const float4*)(pos_tab + (size_t)t * DD);
        float4 pos0 = __ldg(pp + lane);
        float4 pos1 = __ldg(pp + lane + 32);
        float4 pos2 = __ldg(pp + lane + 64);
        float4 pos3 = __ldg(pp + lane + 96);
        const float4 pos[4] = { pos0, pos1, pos2, pos3 };

        #pragma unroll 1
        for (int j = 0; j < 4; j++) {
            const unsigned w = __shfl_sync(0xffffffffu, prl, j);
            const int tok = w >> 16;
            const int r = w & 0xff;
            const int c = (w >> 8) & 0xff;
            const int ci = (tok <= 9) ? (tok * 900 + r * 30 + c)
                                      : (9000 + tok - 10);
            const float4* cbp = (const float4*)(g_comb + (size_t)ci * DD);

            float4 x[4];
            float sum = 0.f, sq = 0.f;
            #pragma unroll
            for (int i = 0; i < 4; i++) {
                float4 a = __ldg(cbp + lane + i * 32);
                float4 v;
                v.x = a.x + pos[i].x;
                v.y = a.y + pos[i].y;
                v.z = a.z + pos[i].z;
                v.w = a.w + pos[i].w;
                x[i] = v;
                sum += (v.x + v.y) + (v.z + v.w);
                sq = fmaf(v.x, v.x, sq);
                sq = fmaf(v.y, v.y, sq);
                sq = fmaf(v.z, v.z, sq);
                sq = fmaf(v.w, v.w, sq);
            }

            #pragma unroll
            for (int o = 16; o > 0; o >>= 1) {
                sum += __shfl_xor_sync(0xffffffffu, sum, o);
                sq  += __shfl_xor_sync(0xffffffffu, sq,  o);
            }

            const float mu = sum * (1.f / (float)DD);
            const float var = sq * (1.f / (float)DD) - mu * mu;
            const float inv = rsqrtf(var + 1e-5f);
            const float nb = -mu * inv;   // (x - mu)*inv = x*inv + nb

            float4* op = (float4*)(out + (size_t)((q * 4 + j) * TT + t) * DD);
            #pragma unroll
            for (int i = 0; i < 4; i++) {
                float4 v = x[i];
                v.x = fmaf(fmaf(v.x, inv, nb), gm[i].x, bt[i].x);
                v.y = fmaf(fmaf(v.y, inv, nb), gm[i].y, bt[i].y);
                v.z = fmaf(fmaf(v.z, inv, nb), gm[i].z, bt[i].z);
                v.w = fmaf(fmaf(v.w, inv, nb), gm[i].w, bt[i].w);
                __stcs(op + lane + i * 32, v);
            }
        }
    }

    // ======================= FLAG RESET (replay-safe) =======================
    __syncthreads();
    if (tid == 0) {
        __threadfence();
        if (atomicAdd(&g_done, 1u) == GRID - 1) {
            g_scan_flag = 0;
            g_pre_flag = 0;
            g_comb_flag = 0;
            __threadfence();
            g_done = 0;
        }
    }
}

// ---------------------------------------------------------------------------
extern "C" void kernel_launch(void* const* d_in, const int* in_sizes, int n_in,
                              void* d_out, int out_size) {
    const int*   ids   = (const int*)  d_in[0];
    const float* tokt  = (const float*)d_in[1];
    const float* post  = (const float*)d_in[2];
    const float* rowt  = (const float*)d_in[3];
    const float* colt  = (const float*)d_in[4];
    const float* W     = (const float*)d_in[5];
    const float* gamma = (const float*)d_in[6];
    const float* beta  = (const float*)d_in[7];
    float* out = (float*)d_out;
    (void)in_sizes; (void)n_in; (void)out_size;

    const int smem_bytes = 60 * 256 * 4;   // 61,440 B (covers scan's 16.5KB too)
    cudaFuncSetAttribute(fused_kernel,
                         cudaFuncAttributeMaxDynamicSharedMemorySize, smem_bytes);

    fused_kernel<<<GRID, NTHR, smem_bytes>>>(ids, rowt, colt, W,
                                             tokt, post, gamma, beta, out);
}

// round 13
// speedup vs baseline: 1.2001x; 1.0007x over previous
#include <cuda_runtime.h>

#define BB 16
#define TT 4096
#define DD 512
#define GRID 148
#define NTHR 1024
#define NWARP 32
#define NCOMB 9005   // 10*30*30 digit combos + 5 non-digit tokens

// PAD=10, BOS=11, EOS=12, ROW=13, SEP=14; digits 0..9

__device__ unsigned g_rc_t[TT * BB];        // [t][b] : r | c<<8 | tok<<16
__device__ float g_srow[30 * DD];
__device__ float g_scol[30 * DD];
__device__ float g_comb[(size_t)NCOMB * DD];   // 18.44 MB, L2-resident
__device__ unsigned g_scan_flag = 0;
__device__ unsigned g_pre_flag = 0;
__device__ unsigned g_comb_flag = 0;
__device__ unsigned g_done = 0;

// ---------------------------------------------------------------------------
// Packed transition-function monoid (2 words)
// ---------------------------------------------------------------------------
struct P { unsigned a, b; };

__device__ __forceinline__ P pidentity() { P p; p.a = 2u; p.b = 0u; return p; }

__device__ __forceinline__ P pcompose(P x, P y) {   // apply x, then y
    unsigned xg0 = x.a & 1u, xg1 = (x.a >> 1) & 1u;
    unsigned yg0 = y.a & 1u, yg1 = (y.a >> 1) & 1u;
    unsigned g0 = xg0 ? yg1 : yg0;
    unsigned g1 = xg1 ? yg1 : yg0;
    unsigned yrC = y.a & 4u;
    unsigned rV = yrC ? (y.a >> 8) : ((x.a >> 8) + (y.a >> 8));
    unsigned rC = (x.a & 4u) | yrC;
    unsigned xc0C = (x.a >> 3) & 1u, xc1C = (x.a >> 4) & 1u;
    unsigned yc0C = (y.a >> 3) & 1u, yc1C = (y.a >> 4) & 1u;
    unsigned xc0 = x.b & 0xffffu, xc1 = x.b >> 16;
    unsigned yc0 = y.b & 0xffffu, yc1 = y.b >> 16;
    unsigned bC0 = xg0 ? yc1C : yc0C;
    unsigned bV0 = xg0 ? yc1  : yc0;
    unsigned c0C = bC0 | xc0C;
    unsigned c0  = bC0 ? bV0 : xc0 + bV0;
    unsigned bC1 = xg1 ? yc1C : yc0C;
    unsigned bV1 = xg1 ? yc1  : yc0;
    unsigned c1C = bC1 | xc1C;
    unsigned c1  = bC1 ? bV1 : xc1 + bV1;
    P r;
    r.a = g0 | (g1 << 1) | rC | (c0C << 3) | (c1C << 4) | (rV << 8);
    r.b = c0 | (c1 << 16);
    return r;
}

__device__ __forceinline__ P pshfl_up(P p, int off) {
    P r;
    r.a = __shfl_up_sync(0xffffffffu, p.a, off);
    r.b = __shfl_up_sync(0xffffffffu, p.b, off);
    return r;
}

// ---------------------------------------------------------------------------
// Fused persistent kernel. grid=148, 1024 thr (32 warps), ~62KB smem.
// Phases: [role: scan | srow/scol] -> [all: build g_comb] -> [all: main].
// gamma/beta live in smem (top of s_raw region, disjoint from prep usage).
// ---------------------------------------------------------------------------
__global__ void __launch_bounds__(NTHR, 1) fused_kernel(
    const int* __restrict__ ids,
    const float* __restrict__ row_tab,   // (30, 256)
    const float* __restrict__ col_tab,   // (30, 256)
    const float* __restrict__ W,         // (512, 512) e-major
    const float* __restrict__ tok_tab,   // (15, 512)
    const float* __restrict__ pos_tab,   // (4096, 512)
    const float* __restrict__ gamma,
    const float* __restrict__ beta,
    float* __restrict__ out)
{
    extern __shared__ __align__(16) char s_raw[];
    const int tid = threadIdx.x;
    const int lane = tid & 31;
    const int warp = tid >> 5;

    // gamma/beta staging area: last 4KB of the 65.5KB smem block
    float4* gb_s = (float4*)(s_raw + 61440);   // [256] float4: gamma | beta
    if (tid < 128) gb_s[tid] = ((const float4*)gamma)[tid];
    else if (tid < 256) gb_s[tid] = ((const float4*)beta)[tid - 128];

    // ======================= ROLE PHASE =======================
    if (blockIdx.x < 16) {
        // ---------------- SCAN (512 active threads, 8 tok/thr) ----------------
        int* toks = (int*)s_raw;                   // [4096]
        P* warpTot = (P*)(s_raw + TT * 4);         // [16]
        P* warpPreInc = warpTot + 16;              // [16]

        const int b = blockIdx.x;
        const int* base = ids + b * TT;
        for (int i = tid; i < TT; i += NTHR) toks[i] = base[i];
        __syncthreads();

        P inc;
        if (tid < 512) {
            const int* my = toks + tid * 8;
            int fg0 = 0, fg1 = 1, frC = 0, frV = 0;
            int fc0C = 0, fc0 = 0, fc1C = 0, fc1 = 0;
            #pragma unroll
            for (int j = 0; j < 8; j++) {
                int tok = my[j];
                int bos = (tok == 11), sep = (tok == 14), rw = (tok == 13);
                int end = (tok == 12) | (tok == 10);
                int dig = (tok <= 9);
                if (bos | sep) { frC = 1; frV = 0; }
                else if (rw) frV++;
                {
                    int gc = fg0 & dig;
                    if (bos | sep | rw) { fc0C = 1; fc0 = 0; }
                    else if (gc) fc0++;
                    fg0 = bos ? 1 : (end ? 0 : fg0);
                }
                {
                    int gc = fg1 & dig;
                    if (bos | sep | rw) { fc1C = 1; fc1 = 0; }
                    else if (gc) fc1++;
                    fg1 = bos ? 1 : (end ? 0 : fg1);
                }
            }
            inc.a = (unsigned)fg0 | ((unsigned)fg1 << 1) | ((unsigned)frC << 2)
                  | ((unsigned)fc0C << 3) | ((unsigned)fc1C << 4) | ((unsigned)frV << 8);
            inc.b = (unsigned)fc0 | ((unsigned)fc1 << 16);

            #pragma unroll
            for (int off = 1; off < 32; off <<= 1) {
                P prev = pshfl_up(inc, off);
                if (lane >= off) inc = pcompose(prev, inc);
            }
            if (lane == 31) warpTot[warp] = inc;
        }
        __syncthreads();

        if (tid < 32) {
            P v = (tid < 16) ? warpTot[tid] : pidentity();
            #pragma unroll
            for (int off = 1; off < 16; off <<= 1) {
                P prev = pshfl_up(v, off);
                if (lane >= off) v = pcompose(prev, v);
            }
            if (tid < 16) warpPreInc[tid] = v;
        }
        __syncthreads();

        if (tid < 512) {
            P wex = pshfl_up(inc, 1);
            P base_p = (warp > 0) ? warpPreInc[warp - 1] : pidentity();
            P ex = (lane > 0) ? pcompose(base_p, wex) : base_p;
            int g = (int)(ex.a & 1u);
            int r = (int)(ex.a >> 8);
            int c = (int)(ex.b & 0xffffu);

            const int* my = toks + tid * 8;
            #pragma unroll
            for (int j = 0; j < 8; j++) {
                int tok = my[j];
                int bos = (tok == 11), sep = (tok == 14), rw = (tok == 13);
                int end = (tok == 12) | (tok == 10);
                int dig = (tok <= 9);
                int gc = g & dig;
                unsigned er = gc ? (unsigned)min(r, 29) : 0u;
                unsigned ec = gc ? (unsigned)min(c, 29) : 0u;
                g_rc_t[(tid * 8 + j) * BB + b] = er | (ec << 8) | ((unsigned)tok << 16);
                g = bos ? 1 : (end ? 0 : g);
                r = (bos | sep) ? 0 : (rw ? r + 1 : r);
                c = (bos | sep | rw) ? 0 : (gc ? c + 1 : c);
            }
        }
        __threadfence();
        __syncthreads();
        if (tid == 0) atomicAdd(&g_scan_flag, 1u);
    } else if (blockIdx.x < 80) {
        // ---------------- srow/scol PRECOMPUTE (W read once total) ----------------
        float* tabs = (float*)s_raw;   // [60*256] : row_tab then col_tab
        {
            float4* t4 = (float4*)tabs;
            const float4* r4 = (const float4*)row_tab;
            const float4* c4 = (const float4*)col_tab;
            for (int i = tid; i < 30 * 64; i += NTHR) t4[i] = r4[i];
            for (int i = tid; i < 30 * 64; i += NTHR) t4[30 * 64 + i] = c4[i];
        }
        __syncthreads();

        const int task = (blockIdx.x - 16) * 16 + warp;   // 64 blocks x 16 warps
        if (warp < 16 && task < 1024) {
            const int e = task >> 1;
            const int half = task & 1;
            const float4* wp = (const float4*)(W + (size_t)e * DD + half * 256);
            const float4 w0 = __ldg(wp + lane * 2);
            const float4 w1 = __ldg(wp + lane * 2 + 1);
            float* dst = half ? g_scol : g_srow;
            const float* tb = tabs + half * 30 * 256;

            #pragma unroll 1
            for (int r = 0; r < 30; r += 2) {
                const float4* ta = (const float4*)(tb + r * 256);
                const float4* tc = (const float4*)(tb + (r + 1) * 256);
                float4 a0 = ta[lane * 2], a1 = ta[lane * 2 + 1];
                float4 b0 = tc[lane * 2], b1 = tc[lane * 2 + 1];
                float sA = a0.x * w0.x;
                sA = fmaf(a0.y, w0.y, sA); sA = fmaf(a0.z, w0.z, sA); sA = fmaf(a0.w, w0.w, sA);
                sA = fmaf(a1.x, w1.x, sA); sA = fmaf(a1.y, w1.y, sA);
                sA = fmaf(a1.z, w1.z, sA); sA = fmaf(a1.w, w1.w, sA);
                float sB = b0.x * w0.x;
                sB = fmaf(b0.y, w0.y, sB); sB = fmaf(b0.z, w0.z, sB); sB = fmaf(b0.w, w0.w, sB);
                sB = fmaf(b1.x, w1.x, sB); sB = fmaf(b1.y, w1.y, sB);
                sB = fmaf(b1.z, w1.z, sB); sB = fmaf(b1.w, w1.w, sB);
                #pragma unroll
                for (int o = 16; o > 0; o >>= 1) {
                    sA += __shfl_xor_sync(0xffffffffu, sA, o);
                    sB += __shfl_xor_sync(0xffffffffu, sB, o);
                }
                if (lane == 0) {
                    dst[r * DD + e] = sA;
                    dst[(r + 1) * DD + e] = sB;
                }
            }
        }
        __threadfence();
        __syncthreads();
        if (tid == 0) atomicAdd(&g_pre_flag, 1u);
    }

    // ======================= BUILD COMBINED TABLE =======================
    if (tid == 0) {
        while (*(volatile unsigned*)&g_pre_flag < 64u) __nanosleep(64);
    }
    __syncthreads();
    {
        const int grp = tid >> 7;        // 8 groups of 128 threads
        const int gt = tid & 127;        // float4 index within row
        for (int combo = blockIdx.x * 8 + grp; combo < NCOMB; combo += GRID * 8) {
            float4* dst = (float4*)(g_comb + (size_t)combo * DD);
            if (combo < 9000) {
                const int tok = combo / 900;
                const int rem = combo - tok * 900;
                const int r = rem / 30;
                const int c = rem - r * 30;
                float4 t = __ldg((const float4*)(tok_tab + tok * DD) + gt);
                float4 rr = __ldcg((const float4*)(g_srow + r * DD) + gt);
                float4 cc = __ldcg((const float4*)(g_scol + c * DD) + gt);
                float4 v;
                v.x = t.x + rr.x + cc.x;
                v.y = t.y + rr.y + cc.y;
                v.z = t.z + rr.z + cc.z;
                v.w = t.w + rr.w + cc.w;
                dst[gt] = v;
            } else {
                const int tok = combo - 9000 + 10;
                dst[gt] = __ldg((const float4*)(tok_tab + tok * DD) + gt);
            }
        }
    }
    __threadfence();
    __syncthreads();
    if (tid == 0) {
        atomicAdd(&g_comb_flag, 1u);
        while (*(volatile unsigned*)&g_comb_flag < (unsigned)GRID) __nanosleep(64);
        while (*(volatile unsigned*)&g_scan_flag < 16u) __nanosleep(64);
    }
    __syncthreads();

    // ======================= MAIN LOOP =======================
    const float4* gam_s = gb_s;
    const float4* bet_s = gb_s + 128;
    const int gw = warp * GRID + blockIdx.x;   // transposed striping
    const int NW = GRID * NWARP;               // 4736 warps

    for (int u = gw; u < TT * 4; u += NW) {
        const int t = u >> 2;
        const int q = u & 3;

        unsigned prl = 0;
        if (lane < 4) prl = __ldcg(g_rc_t + t * BB + q * 4 + lane);
        const float4* pp = (const float4*)(pos_tab + (size_t)t * DD);
        float4 pos0 = __ldg(pp + lane);
        float4 pos1 = __ldg(pp + lane + 32);
        float4 pos2 = __ldg(pp + lane + 64);
        float4 pos3 = __ldg(pp + lane + 96);
        const float4 pos[4] = { pos0, pos1, pos2, pos3 };

        #pragma unroll 1
        for (int j = 0; j < 4; j++) {
            const unsigned w = __shfl_sync(0xffffffffu, prl, j);
            const int tok = w >> 16;
            const int r = w & 0xff;
            const int c = (w >> 8) & 0xff;
            const int ci = (tok <= 9) ? (tok * 900 + r * 30 + c)
                                      : (9000 + tok - 10);
            const float4* cbp = (const float4*)(g_comb + (size_t)ci * DD);

            float4 x[4];
            float sum = 0.f, sq = 0.f;
            #pragma unroll
            for (int i = 0; i < 4; i++) {
                float4 a = __ldg(cbp + lane + i * 32);
                float4 v;
                v.x = a.x + pos[i].x;
                v.y = a.y + pos[i].y;
                v.z = a.z + pos[i].z;
                v.w = a.w + pos[i].w;
                x[i] = v;
                sum += (v.x + v.y) + (v.z + v.w);
                sq = fmaf(v.x, v.x, sq);
                sq = fmaf(v.y, v.y, sq);
                sq = fmaf(v.z, v.z, sq);
                sq = fmaf(v.w, v.w, sq);
            }

            #pragma unroll
            for (int o = 16; o > 0; o >>= 1) {
                sum += __shfl_xor_sync(0xffffffffu, sum, o);
                sq  += __shfl_xor_sync(0xffffffffu, sq,  o);
            }

            const float mu = sum * (1.f / (float)DD);
            const float var = sq * (1.f / (float)DD) - mu * mu;
            const float inv = rsqrtf(var + 1e-5f);
            const float nb = -mu * inv;   // (x - mu)*inv = x*inv + nb

            float4* op = (float4*)(out + (size_t)((q * 4 + j) * TT + t) * DD);
            #pragma unroll
            for (int i = 0; i < 4; i++) {
                const int idx = lane + i * 32;
                float4 gmv = gam_s[idx];
                float4 btv = bet_s[idx];
                float4 v = x[i];
                v.x = fmaf(fmaf(v.x, inv, nb), gmv.x, btv.x);
                v.y = fmaf(fmaf(v.y, inv, nb), gmv.y, btv.y);
                v.z = fmaf(fmaf(v.z, inv, nb), gmv.z, btv.z);
                v.w = fmaf(fmaf(v.w, inv, nb), gmv.w, btv.w);
                __stcs(op + idx, v);
            }
        }
    }

    // ======================= FLAG RESET (replay-safe) =======================
    __syncthreads();
    if (tid == 0) {
        __threadfence();
        if (atomicAdd(&g_done, 1u) == GRID - 1) {
            g_scan_flag = 0;
            g_pre_flag = 0;
            g_comb_flag = 0;
            __threadfence();
            g_done = 0;
        }
    }
}

// ---------------------------------------------------------------------------
extern "C" void kernel_launch(void* const* d_in, const int* in_sizes, int n_in,
                              void* d_out, int out_size) {
    const int*   ids   = (const int*)  d_in[0];
    const float* tokt  = (const float*)d_in[1];
    const float* post  = (const float*)d_in[2];
    const float* rowt  = (const float*)d_in[3];
    const float* colt  = (const float*)d_in[4];
    const float* W     = (const float*)d_in[5];
    const float* gamma = (const float*)d_in[6];
    const float* beta  = (const float*)d_in[7];
    float* out = (float*)d_out;
    (void)in_sizes; (void)n_in; (void)out_size;

    const int smem_bytes = 61440 + 4096;   // prep region + gamma/beta = 65,536 B
    cudaFuncSetAttribute(fused_kernel,
                         cudaFuncAttributeMaxDynamicSharedMemorySize, smem_bytes);

    fused_kernel<<<GRID, NTHR, smem_bytes>>>(ids, rowt, colt, W,
                                             tokt, post, gamma, beta, out);
}